// round 15
// baseline (speedup 1.0000x reference)
#include <cuda_runtime.h>
#include <cstdint>

// Problem dims
#define TT 2048
#define BB 16
#define DM 1024
#define DB 128
#define DH 512
#define RWS (TT*BB)                 // 32768 rows
#define OUT_MAIN ((size_t)RWS*DM)   // offset of final_mem in d_out

#define NCH 64                      // scan chunks
#define CHLEN (TT/NCH)              // 32
#define LANES (BB*DB)               // 2048 scan lanes

#define ASTAT_SMEM ((8 + 4) * 2048 * 4)   // 98304 bytes: A[8 tiles] + B[4-ring]

// Scratch (device globals; no runtime allocation allowed)
__device__ float g_H   [RWS*DB];
__device__ float g_Wpre[RWS*DB];
__device__ float g_M   [RWS*DB];
__device__ float g_G   [RWS*DB];
__device__ float g_U1  [RWS*DH];
__device__ float g_G2  [RWS*DB];
__device__ float g_UP  [RWS*DM];
__device__ float g_Aseg [NCH*LANES];
__device__ float g_Cseg [NCH*LANES];
__device__ float g_Carry[NCH*LANES];
// transformed weights: [N][K], k-permuted+swizzled, tf32-truncated
__device__ float g_WbT [DB*DM];
__device__ float g_WwT [DB*DB];
__device__ float g_WrT [DB*DB];
__device__ float g_W1T [DH*DB];
__device__ float g_W2T [DB*DH];
__device__ float g_WuT [DM*DB];

// ---------------------------------------------------------------------------
__device__ __forceinline__ float to_tf32(float x) {
    uint32_t u;
    asm("cvt.rna.tf32.f32 %0, %1;" : "=r"(u) : "f"(x));
    return __uint_as_float(u);
}

__device__ __forceinline__ void mma_tf32(float* d, const float* a, const float* b) {
    asm volatile(
        "mma.sync.aligned.m16n8k8.row.col.f32.tf32.tf32.f32 "
        "{%0,%1,%2,%3}, {%4,%5,%6,%7}, {%8,%9}, {%0,%1,%2,%3};"
        : "+f"(d[0]), "+f"(d[1]), "+f"(d[2]), "+f"(d[3])
        : "r"(__float_as_uint(a[0])), "r"(__float_as_uint(a[1])),
          "r"(__float_as_uint(a[2])), "r"(__float_as_uint(a[3])),
          "r"(__float_as_uint(b[0])), "r"(__float_as_uint(b[1])));
}

__device__ __forceinline__ void cp_async16(void* smem_dst, const void* gmem_src) {
    unsigned dst = (unsigned)__cvta_generic_to_shared(smem_dst);
    asm volatile("cp.async.ca.shared.global [%0], [%1], 16;" :: "r"(dst), "l"(gmem_src));
}
__device__ __forceinline__ void cp_async_commit() {
    asm volatile("cp.async.commit_group;");
}
__device__ __forceinline__ void cp_async_wait1() {
    asm volatile("cp.async.wait_group 1;" ::: "memory");
}
__device__ __forceinline__ void cp_async_wait2() {
    asm volatile("cp.async.wait_group 2;" ::: "memory");
}
__device__ __forceinline__ void cp_async_wait_all() {
    asm volatile("cp.async.wait_group 0;" ::: "memory");
}

// ---------------------------------------------------------------------------
// Weight prep: Wt[n][pos(k)] = tf32(W[k][n]), pos within 16-k groups:
//   kk=k&15: pos = g*16 + ((kk&3) ^ ((n>>1)&3))*4 + (kk>>2)
// ---------------------------------------------------------------------------
__global__ void prep_weights(const float* __restrict__ Wb, const float* __restrict__ Ww,
                             const float* __restrict__ Wr, const float* __restrict__ W1,
                             const float* __restrict__ W2, const float* __restrict__ Wu,
                             float* __restrict__ WbT, float* __restrict__ WwT,
                             float* __restrict__ WrT, float* __restrict__ W1T,
                             float* __restrict__ W2T, float* __restrict__ WuT)
{
    const int wsel = blockIdx.y;
    const float* W; float* Wt; int K, N;
    switch (wsel) {
        case 0: W = Wb; Wt = WbT; K = DM; N = DB; break;
        case 1: W = Ww; Wt = WwT; K = DB; N = DB; break;
        case 2: W = Wr; Wt = WrT; K = DB; N = DB; break;
        case 3: W = W1; Wt = W1T; K = DB; N = DH; break;
        case 4: W = W2; Wt = W2T; K = DH; N = DB; break;
        default: W = Wu; Wt = WuT; K = DB; N = DM; break;
    }
    const int idx = blockIdx.x * blockDim.x + threadIdx.x;
    if (idx >= K * N) return;
    const int k = idx / N, n = idx % N;
    const int kk = k & 15, g = k >> 4;
    const int pos = g * 16 + (((kk & 3) ^ ((n >> 1) & 3)) << 2) + (kk >> 2);
    Wt[(size_t)n * K + pos] = to_tf32(W[idx]);
}

// ---------------------------------------------------------------------------
// Shared compute for one k-tile (BM=128, BN=128, BK=16 layout)
// ---------------------------------------------------------------------------
#define COMPUTE_TILE(as_, bs_)                                                  \
    {                                                                           \
        float4 a0[2], a1[2];                                                    \
        _Pragma("unroll")                                                       \
        for (int mt = 0; mt < 2; mt++) {                                        \
            const int r0 = wm * 32 + mt * 16 + gid;                             \
            const int r1 = r0 + 8;                                              \
            a0[mt] = *(const float4*)&(as_)[r0 * 16 + ((tig ^ ((r0 >> 1) & 3)) << 2)]; \
            a1[mt] = *(const float4*)&(as_)[r1 * 16 + ((tig ^ ((r1 >> 1) & 3)) << 2)]; \
        }                                                                       \
        _Pragma("unroll")                                                       \
        for (int nh = 0; nh < 2; nh++) {                                        \
            float4 b4[4];                                                       \
            _Pragma("unroll")                                                   \
            for (int q = 0; q < 4; q++) {                                       \
                const int n = wn * 64 + (nh * 4 + q) * 8 + gid;                 \
                b4[q] = *(const float4*)&(bs_)[n * 16 + ((tig ^ ((n >> 1) & 3)) << 2)]; \
            }                                                                   \
            _Pragma("unroll")                                                   \
            for (int ph = 0; ph < 2; ph++) {                                    \
                _Pragma("unroll")                                               \
                for (int mt = 0; mt < 2; mt++) {                                \
                    float af[4];                                                \
                    if (ph == 0) { af[0] = a0[mt].x; af[1] = a1[mt].x;          \
                                   af[2] = a0[mt].y; af[3] = a1[mt].y; }        \
                    else         { af[0] = a0[mt].z; af[1] = a1[mt].z;          \
                                   af[2] = a0[mt].w; af[3] = a1[mt].w; }        \
                    _Pragma("unroll")                                           \
                    for (int q = 0; q < 4; q++) {                               \
                        float bf[2];                                            \
                        bf[0] = (ph == 0) ? b4[q].x : b4[q].z;                  \
                        bf[1] = (ph == 0) ? b4[q].y : b4[q].w;                  \
                        mma_tf32(acc[mt][nh * 4 + q], af, bf);                  \
                    }                                                           \
                }                                                               \
            }                                                                   \
        }                                                                       \
    }

// Pair (k, k+4) of a 16-k group lands at adjacent smem offsets -> float2 store.
#define A_STORE(dst, row, q2, sw, v0, v1)                                       \
    {                                                                           \
        float* as_ = (dst) + (row) * 16;                                        \
        *(float2*)&as_[((0 ^ (sw)) << 2) + (q2)] =                              \
            make_float2(to_tf32((v0).x), to_tf32((v1).x));                      \
        *(float2*)&as_[((1 ^ (sw)) << 2) + (q2)] =                              \
            make_float2(to_tf32((v0).y), to_tf32((v1).y));                      \
        *(float2*)&as_[((2 ^ (sw)) << 2) + (q2)] =                              \
            make_float2(to_tf32((v0).z), to_tf32((v1).z));                      \
        *(float2*)&as_[((3 ^ (sw)) << 2) + (q2)] =                              \
            make_float2(to_tf32((v0).w), to_tf32((v1).w));                      \
    }

// ---------------------------------------------------------------------------
// TF32 GEMM: C = act(A@W + bias) (+optional fused residual+LN128).
// A: register-staged double buffer. B: 3-stage cp.async ring (distance 2).
// ---------------------------------------------------------------------------
template<int ACT, int FUSE_LN>
__global__ void __launch_bounds__(256)
gemm_tf32(const float* __restrict__ A, const float* __restrict__ Wt,
          const float* __restrict__ bias,
          const float* __restrict__ resid,
          const float* __restrict__ ln_s, const float* __restrict__ ln_b,
          float* __restrict__ C, int M, int N, int K)
{
    __shared__ __align__(16) float As[2][128 * 16];
    __shared__ __align__(16) float Bs[3][128 * 16];
    __shared__ float2 red[128][2];

    const int tid  = threadIdx.x;
    const int warp = tid >> 5, lane = tid & 31;
    const int gid  = lane >> 2, tig = lane & 3;
    const int wm   = warp >> 1, wn = warp & 1;
    const int bm   = blockIdx.y, bn = blockIdx.x;

    const float* Ablk = A + (size_t)bm * 128 * K;

    const int aRow = tid >> 1;
    const int aQ   = (tid & 1) * 2;
    const int aSw  = (aRow >> 1) & 3;
    const int bN   = tid >> 1;
    const int bC   = (tid & 1) * 2;
    const float* Bsrc = Wt + (size_t)(bn * 128 + bN) * K + bC * 4;

    float acc[2][8][4];
#pragma unroll
    for (int mt = 0; mt < 2; mt++)
#pragma unroll
        for (int nt = 0; nt < 8; nt++)
#pragma unroll
            for (int i = 0; i < 4; i++) acc[mt][nt][i] = 0.f;

    const int nt_tiles = K >> 4;

    // prologue: B0, B1 (distance-2), A0
    {
        cp_async16(&Bs[0][bN * 16 + bC * 4],     Bsrc);
        cp_async16(&Bs[0][bN * 16 + bC * 4 + 4], Bsrc + 4);
        cp_async_commit();
        if (nt_tiles > 1) {
            cp_async16(&Bs[1][bN * 16 + bC * 4],     Bsrc + 16);
            cp_async16(&Bs[1][bN * 16 + bC * 4 + 4], Bsrc + 16 + 4);
        }
        cp_async_commit();
        float4 va0 = *(const float4*)(Ablk + (size_t)aRow * K + aQ * 4);
        float4 va1 = *(const float4*)(Ablk + (size_t)aRow * K + aQ * 4 + 4);
        A_STORE(As[0], aRow, aQ, aSw, va0, va1);
        cp_async_wait1();          // B0 complete (newest 1 = B1 group)
    }
    __syncthreads();

    int buf = 0;
    int bslot = 0;
    for (int t = 0; t < nt_tiles; t++) {
        const bool has_next = (t + 1) < nt_tiles;
        float4 na0, na1;
        if (has_next) {
            const int k0n = (t + 1) << 4;
            na0 = *(const float4*)(Ablk + (size_t)aRow * K + k0n + aQ * 4);
            na1 = *(const float4*)(Ablk + (size_t)aRow * K + k0n + aQ * 4 + 4);
        }
        // prefetch B[t+2] into ring slot (distance 2)
        if (t + 2 < nt_tiles) {
            const int ks = (t + 2) << 4;
            int ns = bslot + 2; if (ns >= 3) ns -= 3;
            cp_async16(&Bs[ns][bN * 16 + bC * 4],     Bsrc + ks);
            cp_async16(&Bs[ns][bN * 16 + bC * 4 + 4], Bsrc + ks + 4);
        }
        cp_async_commit();         // one group per tile (possibly empty)

        const float* as_ = As[buf];
        const float* bs_ = Bs[bslot];
        COMPUTE_TILE(as_, bs_);

        if (has_next) {
            A_STORE(As[buf ^ 1], aRow, aQ, aSw, na0, na1);
            cp_async_wait1();      // B[t+1] complete (newest 1 = this tile's commit)
            __syncthreads();
            buf ^= 1;
            if (++bslot == 3) bslot = 0;
        }
    }

    // ---------------- Epilogue ----------------
    if (FUSE_LN) {
        float sum[2][2], sq[2][2];
#pragma unroll
        for (int mt = 0; mt < 2; mt++) { sum[mt][0] = sum[mt][1] = 0.f; sq[mt][0] = sq[mt][1] = 0.f; }

#pragma unroll
        for (int mt = 0; mt < 2; mt++) {
            const int gr0 = bm * 128 + wm * 32 + mt * 16 + gid;
#pragma unroll
            for (int nt = 0; nt < 8; nt++) {
                const int c0 = wn * 64 + nt * 8 + 2 * tig;
                const float bi0 = bias[c0], bi1 = bias[c0 + 1];
                const float2 rA = *(const float2*)(resid + (size_t)gr0 * 128 + c0);
                const float2 rB = *(const float2*)(resid + (size_t)(gr0 + 8) * 128 + c0);
                acc[mt][nt][0] += bi0 + rA.x;
                acc[mt][nt][1] += bi1 + rA.y;
                acc[mt][nt][2] += bi0 + rB.x;
                acc[mt][nt][3] += bi1 + rB.y;
#pragma unroll
                for (int h = 0; h < 2; h++) {
                    const float v0 = acc[mt][nt][2 * h], v1 = acc[mt][nt][2 * h + 1];
                    sum[mt][h] += v0 + v1;
                    sq[mt][h]  += v0 * v0 + v1 * v1;
                }
            }
        }
#pragma unroll
        for (int mt = 0; mt < 2; mt++)
#pragma unroll
            for (int h = 0; h < 2; h++) {
#pragma unroll
                for (int off = 1; off <= 2; off <<= 1) {
                    sum[mt][h] += __shfl_xor_sync(0xffffffffu, sum[mt][h], off);
                    sq[mt][h]  += __shfl_xor_sync(0xffffffffu, sq[mt][h], off);
                }
            }
        if (tig == 0) {
#pragma unroll
            for (int mt = 0; mt < 2; mt++) {
                const int lr0 = wm * 32 + mt * 16 + gid;
                red[lr0][wn]     = make_float2(sum[mt][0], sq[mt][0]);
                red[lr0 + 8][wn] = make_float2(sum[mt][1], sq[mt][1]);
            }
        }
        __syncthreads();

#pragma unroll
        for (int mt = 0; mt < 2; mt++) {
            const int lr0 = wm * 32 + mt * 16 + gid;
            const int gr0 = bm * 128 + lr0;
#pragma unroll
            for (int h = 0; h < 2; h++) {
                const int lr = lr0 + 8 * h;
                const float2 t0 = red[lr][0], t1 = red[lr][1];
                const float mean = (t0.x + t1.x) * (1.f / 128.f);
                const float var  = (t0.y + t1.y) * (1.f / 128.f) - mean * mean;
                const float inv  = rsqrtf(var + 1e-5f);
                float* cp = C + (size_t)(gr0 + 8 * h) * 128;
#pragma unroll
                for (int nt = 0; nt < 8; nt++) {
                    const int c0 = wn * 64 + nt * 8 + 2 * tig;
                    const float s0 = ln_s[c0], s1 = ln_s[c0 + 1];
                    const float b0 = ln_b[c0], b1 = ln_b[c0 + 1];
                    float2 ov;
                    ov.x = (acc[mt][nt][2 * h]     - mean) * inv * s0 + b0;
                    ov.y = (acc[mt][nt][2 * h + 1] - mean) * inv * s1 + b1;
                    *(float2*)(cp + c0) = ov;
                }
            }
        }
    } else {
#pragma unroll
        for (int mt = 0; mt < 2; mt++) {
            const int r0 = bm * 128 + wm * 32 + mt * 16 + gid;
#pragma unroll
            for (int nt = 0; nt < 8; nt++) {
                const int c0 = bn * 128 + wn * 64 + nt * 8 + 2 * tig;
                const float bi0 = bias[c0], bi1 = bias[c0 + 1];
                float v0 = acc[mt][nt][0] + bi0;
                float v1 = acc[mt][nt][1] + bi1;
                float v2 = acc[mt][nt][2] + bi0;
                float v3 = acc[mt][nt][3] + bi1;
                if (ACT == 1) { v0 = tanhf(v0); v1 = tanhf(v1); v2 = tanhf(v2); v3 = tanhf(v3); }
                else if (ACT == 2) { v0 = fmaxf(v0, 0.f); v1 = fmaxf(v1, 0.f); v2 = fmaxf(v2, 0.f); v3 = fmaxf(v3, 0.f); }
                *(float2*)(C + (size_t)r0 * N + c0)       = make_float2(v0, v1);
                *(float2*)(C + (size_t)(r0 + 8) * N + c0) = make_float2(v2, v3);
            }
        }
    }
}

// ---------------------------------------------------------------------------
// A-stationary GEMM (K=128, wide N): stage all 8 A k-tiles once, stream B
// across n-strips via a 4-stage cp.async ring (distance 3). ACT: 0 none, 2 relu.
// ---------------------------------------------------------------------------
template<int ACT>
__global__ void __launch_bounds__(256)
gemm_astat(const float* __restrict__ A, const float* __restrict__ Wt,
           const float* __restrict__ bias, float* __restrict__ C,
           int N, int NS)
{
    extern __shared__ __align__(16) float smem[];
    float* As = smem;              // 8 tiles * 2048
    float* Bs = smem + 8 * 2048;   // 4-ring  * 2048
    const int K = 128;

    const int tid  = threadIdx.x;
    const int warp = tid >> 5, lane = tid & 31;
    const int gid  = lane >> 2, tig = lane & 3;
    const int wm   = warp >> 1, wn = warp & 1;
    const int bm   = blockIdx.y;

    const float* Ablk = A + (size_t)bm * 128 * K;
    const int aRow = tid >> 1;
    const int aQ   = (tid & 1) * 2;
    const int aSw  = (aRow >> 1) & 3;
    const int bN   = tid >> 1;
    const int bC   = (tid & 1) * 2;

    const int qtot = NS * 8;

    // stage ALL A k-tiles once + first 3 B tiles (ring prologue)
    {
#pragma unroll
        for (int p = 0; p < 3; p++) {
            if (p < qtot) {
                const int qs = p >> 3, qt = p & 7;
                const float* bsrc = Wt + (size_t)(qs * 128 + bN) * K + qt * 16 + bC * 4;
                cp_async16(&Bs[p * 2048 + bN * 16 + bC * 4],     bsrc);
                cp_async16(&Bs[p * 2048 + bN * 16 + bC * 4 + 4], bsrc + 4);
            }
            cp_async_commit();
        }
#pragma unroll
        for (int t = 0; t < 8; t++) {
            float4 va0 = *(const float4*)(Ablk + (size_t)aRow * K + t * 16 + aQ * 4);
            float4 va1 = *(const float4*)(Ablk + (size_t)aRow * K + t * 16 + aQ * 4 + 4);
            A_STORE(As + t * 2048, aRow, aQ, aSw, va0, va1);
        }
        cp_async_wait2();          // B[0] complete
    }
    __syncthreads();

    for (int s = 0; s < NS; s++) {
        float acc[2][8][4];
#pragma unroll
        for (int mt = 0; mt < 2; mt++)
#pragma unroll
            for (int nt = 0; nt < 8; nt++)
#pragma unroll
                for (int i = 0; i < 4; i++) acc[mt][nt][i] = 0.f;

#pragma unroll
        for (int t = 0; t < 8; t++) {
            const int q = s * 8 + t;
            // prefetch B[q+3] into ring slot (distance 3); slot = old q-1 buffer,
            // protected by the __syncthreads at the end of tile q-1.
            if (q + 3 < qtot) {
                const int qn = q + 3;
                const int qs2 = qn >> 3, qt2 = qn & 7;
                const float* nb = Wt + (size_t)(qs2 * 128 + bN) * K + qt2 * 16 + bC * 4;
                cp_async16(&Bs[(qn & 3) * 2048 + bN * 16 + bC * 4],     nb);
                cp_async16(&Bs[(qn & 3) * 2048 + bN * 16 + bC * 4 + 4], nb + 4);
            }
            cp_async_commit();     // one group per tile

            const float* as_ = As + t * 2048;
            const float* bs_ = Bs + (q & 3) * 2048;
            COMPUTE_TILE(as_, bs_);

            cp_async_wait2();      // B[q+1] complete (newest 2 = q+2's, q+3's groups)
            __syncthreads();
        }

        // strip epilogue
#pragma unroll
        for (int mt = 0; mt < 2; mt++) {
            const int r0 = bm * 128 + wm * 32 + mt * 16 + gid;
#pragma unroll
            for (int nt = 0; nt < 8; nt++) {
                const int c0 = s * 128 + wn * 64 + nt * 8 + 2 * tig;
                const float bi0 = bias[c0], bi1 = bias[c0 + 1];
                float v0 = acc[mt][nt][0] + bi0;
                float v1 = acc[mt][nt][1] + bi1;
                float v2 = acc[mt][nt][2] + bi0;
                float v3 = acc[mt][nt][3] + bi1;
                if (ACT == 2) { v0 = fmaxf(v0, 0.f); v1 = fmaxf(v1, 0.f); v2 = fmaxf(v2, 0.f); v3 = fmaxf(v3, 0.f); }
                *(float2*)(C + (size_t)r0 * N + c0)       = make_float2(v0, v1);
                *(float2*)(C + (size_t)(r0 + 8) * N + c0) = make_float2(v2, v3);
            }
        }
    }
}

// ---------------------------------------------------------------------------
// Scan (3-pass, float2-vectorized passes 1/3, 2-chunk/lane warp scan in pass2)
// ---------------------------------------------------------------------------
__global__ void scan_pass1(const float* __restrict__ Wpre,
                           const unsigned char* __restrict__ mask,
                           const float* __restrict__ dlogit,
                           float* __restrict__ Aseg, float* __restrict__ Cseg)
{
    const int tid2 = blockIdx.x * blockDim.x + threadIdx.x;  // 0..1023
    const int ch   = blockIdx.y;
    const int b    = tid2 >> 6;
    const int jp   = tid2 & 63;
    const int base = b * 128 + 2 * jp;
    const float2 dl = *(const float2*)(dlogit + 2 * jp);
    const float d0 = 1.f / (1.f + expf(-dl.x)), d1 = 1.f / (1.f + expf(-dl.y));
    float A0 = 1.f, C0 = 0.f, A1 = 1.f, C1 = 0.f;
    const int t0 = ch * CHLEN;
#pragma unroll 4
    for (int t = t0; t < t0 + CHLEN; t++) {
        const bool mk = mask[t * BB + b] != 0;
        const float2 w = *(const float2*)(Wpre + (size_t)t * LANES + base);
        if (!mk) {
            A0 *= d0; C0 = d0 * C0 + (1.f - d0) * w.x;
            A1 *= d1; C1 = d1 * C1 + (1.f - d1) * w.y;
        }
    }
    *(float2*)(Aseg + ch * LANES + base) = make_float2(A0, A1);
    *(float2*)(Cseg + ch * LANES + base) = make_float2(C0, C1);
}

__global__ void scan_pass2(const float* __restrict__ Aseg,
                           const float* __restrict__ Cseg,
                           const float* __restrict__ mem0,
                           float* __restrict__ Carry,
                           float* __restrict__ outFinal)
{
    const int idx  = blockIdx.x * 8 + (threadIdx.x >> 5);
    const int lane = threadIdx.x & 31;
    const float A0 = Aseg[(2 * lane) * LANES + idx];
    const float C0 = Cseg[(2 * lane) * LANES + idx];
    const float A1 = Aseg[(2 * lane + 1) * LANES + idx];
    const float C1 = Cseg[(2 * lane + 1) * LANES + idx];
    float Av = A1 * A0;
    float Cv = A1 * C0 + C1;
#pragma unroll
    for (int off = 1; off < 32; off <<= 1) {
        const float pA = __shfl_up_sync(0xffffffffu, Av, off);
        const float pC = __shfl_up_sync(0xffffffffu, Cv, off);
        if (lane >= off) { Cv = Av * pC + Cv; Av = Av * pA; }
    }
    const float m0 = mem0[idx];
    const float incl = Av * m0 + Cv;
    const float prev = __shfl_up_sync(0xffffffffu, incl, 1);
    const float enter0 = (lane == 0) ? m0 : prev;
    const float enter1 = A0 * enter0 + C0;
    Carry[(2 * lane) * LANES + idx]     = enter0;
    Carry[(2 * lane + 1) * LANES + idx] = enter1;
    if (lane == 31) outFinal[idx] = incl;
}

__global__ void scan_pass3(const float* __restrict__ Wpre,
                           const unsigned char* __restrict__ mask,
                           const float* __restrict__ dlogit,
                           const float* __restrict__ Carry,
                           float* __restrict__ Mbuf)
{
    const int tid2 = blockIdx.x * blockDim.x + threadIdx.x;  // 0..1023
    const int ch   = blockIdx.y;
    const int b    = tid2 >> 6;
    const int jp   = tid2 & 63;
    const int base = b * 128 + 2 * jp;
    const float2 dl = *(const float2*)(dlogit + 2 * jp);
    const float d0 = 1.f / (1.f + expf(-dl.x)), d1 = 1.f / (1.f + expf(-dl.y));
    float2 m = *(const float2*)(Carry + ch * LANES + base);
    const int t0 = ch * CHLEN;
#pragma unroll 4
    for (int t = t0; t < t0 + CHLEN; t++) {
        *(float2*)(Mbuf + (size_t)t * LANES + base) = m;
        const bool mk = mask[t * BB + b] != 0;
        const float2 w = *(const float2*)(Wpre + (size_t)t * LANES + base);
        if (!mk) {
            m.x = d0 * m.x + (1.f - d0) * w.x;
            m.y = d1 * m.y + (1.f - d1) * w.y;
        }
    }
}

// ---------------------------------------------------------------------------
// Final: out = LN(X + UP) over D_MODEL=1024, single-pass stats.
// ---------------------------------------------------------------------------
__global__ void __launch_bounds__(256)
ln_out_kernel(const float* __restrict__ X, const float* __restrict__ UP,
              const float* __restrict__ s, const float* __restrict__ b,
              float* __restrict__ O)
{
    __shared__ float2 red[8];
    const int row = blockIdx.x;
    const int tid = threadIdx.x;
    const int lane = tid & 31, wid = tid >> 5;
    const float4 xv = *(const float4*)(X  + (size_t)row * DM + tid * 4);
    const float4 uv = *(const float4*)(UP + (size_t)row * DM + tid * 4);
    float v[4] = {xv.x + uv.x, xv.y + uv.y, xv.z + uv.z, xv.w + uv.w};
    float2 st = make_float2(0.f, 0.f);
#pragma unroll
    for (int i = 0; i < 4; i++) { st.x += v[i]; st.y += v[i] * v[i]; }
#pragma unroll
    for (int off = 16; off >= 1; off >>= 1) {
        st.x += __shfl_xor_sync(0xffffffffu, st.x, off);
        st.y += __shfl_xor_sync(0xffffffffu, st.y, off);
    }
    if (lane == 0) red[wid] = st;
    __syncthreads();
    float2 t = (lane < 8) ? red[lane] : make_float2(0.f, 0.f);
#pragma unroll
    for (int off = 4; off >= 1; off >>= 1) {
        t.x += __shfl_xor_sync(0xffffffffu, t.x, off);
        t.y += __shfl_xor_sync(0xffffffffu, t.y, off);
    }
    t.x = __shfl_sync(0xffffffffu, t.x, 0);
    t.y = __shfl_sync(0xffffffffu, t.y, 0);
    const float mean = t.x * (1.f / DM);
    const float var  = t.y * (1.f / DM) - mean * mean;
    const float inv  = rsqrtf(var + 1e-5f);
    const float4 sv = *(const float4*)(s + tid * 4);
    const float4 bv = *(const float4*)(b + tid * 4);
    float4 ov;
    ov.x = (v[0] - mean) * inv * sv.x + bv.x;
    ov.y = (v[1] - mean) * inv * sv.y + bv.y;
    ov.z = (v[2] - mean) * inv * sv.z + bv.z;
    ov.w = (v[3] - mean) * inv * sv.w + bv.w;
    *(float4*)(O + (size_t)row * DM + tid * 4) = ov;
}

// ---------------------------------------------------------------------------
extern "C" void kernel_launch(void* const* d_in, const int* in_sizes, int n_in,
                              void* d_out, int out_size)
{
    const float*         x      = (const float*)d_in[0];
    const unsigned char* mask   = (const unsigned char*)d_in[1];
    const float*         mem0   = (const float*)d_in[2];
    const float*         Wb     = (const float*)d_in[3];
    const float*         b_bot  = (const float*)d_in[4];
    const float*         Wu     = (const float*)d_in[5];
    const float*         bu     = (const float*)d_in[6];
    const float*         Wr     = (const float*)d_in[7];
    const float*         br     = (const float*)d_in[8];
    const float*         Ww     = (const float*)d_in[9];
    const float*         bw     = (const float*)d_in[10];
    const float*         dlog   = (const float*)d_in[11];
    const float*         ff_w1  = (const float*)d_in[12];
    const float*         ff_b1  = (const float*)d_in[13];
    const float*         ff_w2  = (const float*)d_in[14];
    const float*         ff_b2  = (const float*)d_in[15];
    const float*         mln_s  = (const float*)d_in[16];
    const float*         mln_b  = (const float*)d_in[17];
    const float*         fln_s  = (const float*)d_in[18];
    const float*         fln_b  = (const float*)d_in[19];
    const float*         oln_s  = (const float*)d_in[20];
    const float*         oln_b  = (const float*)d_in[21];

    float* out = (float*)d_out;

    float *H, *Wpre, *M, *G, *U1, *G2, *UP, *Aseg, *Cseg, *Carry;
    float *WbT, *WwT, *WrT, *W1T, *W2T, *WuT;
    cudaGetSymbolAddress((void**)&H,     g_H);
    cudaGetSymbolAddress((void**)&Wpre,  g_Wpre);
    cudaGetSymbolAddress((void**)&M,     g_M);
    cudaGetSymbolAddress((void**)&G,     g_G);
    cudaGetSymbolAddress((void**)&U1,    g_U1);
    cudaGetSymbolAddress((void**)&G2,    g_G2);
    cudaGetSymbolAddress((void**)&UP,    g_UP);
    cudaGetSymbolAddress((void**)&Aseg,  g_Aseg);
    cudaGetSymbolAddress((void**)&Cseg,  g_Cseg);
    cudaGetSymbolAddress((void**)&Carry, g_Carry);
    cudaGetSymbolAddress((void**)&WbT,   g_WbT);
    cudaGetSymbolAddress((void**)&WwT,   g_WwT);
    cudaGetSymbolAddress((void**)&WrT,   g_WrT);
    cudaGetSymbolAddress((void**)&W1T,   g_W1T);
    cudaGetSymbolAddress((void**)&W2T,   g_W2T);
    cudaGetSymbolAddress((void**)&WuT,   g_WuT);

    static int attr_set = 0;
    if (!attr_set) {
        cudaFuncSetAttribute(gemm_astat<0>, cudaFuncAttributeMaxDynamicSharedMemorySize, ASTAT_SMEM);
        cudaFuncSetAttribute(gemm_astat<2>, cudaFuncAttributeMaxDynamicSharedMemorySize, ASTAT_SMEM);
        attr_set = 1;
    }

    const int MR = RWS;  // 32768 rows

    // 0) transform weights (transpose + k-perm + swizzle + tf32)
    prep_weights<<<dim3(512, 6), 256>>>(Wb, Ww, Wr, ff_w1, ff_w2, Wu,
                                        WbT, WwT, WrT, W1T, W2T, WuT);
    // 1) H = X @ Wb + bb
    gemm_tf32<0,0><<<dim3(1, MR / 128), 256>>>(x, WbT, b_bot, nullptr, nullptr, nullptr,
                                               H, MR, DB, DM);
    // 2) Wpre = tanh(H @ Ww + bw)
    gemm_tf32<1,0><<<dim3(1, MR / 128), 256>>>(H, WwT, bw, nullptr, nullptr, nullptr,
                                               Wpre, MR, DB, DB);
    // 3) parallel diagonal scan -> M[t], final mem
    scan_pass1<<<dim3(4, NCH), 256>>>(Wpre, mask, dlog, Aseg, Cseg);
    scan_pass2<<<LANES / 8, 256>>>(Aseg, Cseg, mem0, Carry, out + OUT_MAIN);
    scan_pass3<<<dim3(4, NCH), 256>>>(Wpre, mask, dlog, Carry, M);
    // 4+5) G = LN(H + M@Wr + br)  [fused LN]
    gemm_tf32<0,1><<<dim3(1, MR / 128), 256>>>(M, WrT, br, H, mln_s, mln_b,
                                               G, MR, DB, DB);
    // 6) U1 = relu(G @ ff_w1 + ff_b1)  [A-stationary, 4 strips]
    gemm_astat<2><<<dim3(1, MR / 128), 256, ASTAT_SMEM>>>(G, W1T, ff_b1, U1, DH, DH / 128);
    // 7+8) G2 = LN(G + U1@ff_w2 + ff_b2)  [fused LN]
    gemm_tf32<0,1><<<dim3(1, MR / 128), 256>>>(U1, W2T, ff_b2, G, fln_s, fln_b,
                                               G2, MR, DB, DH);
    // 9) UP = G2 @ Wu + bu  [A-stationary, 8 strips]
    gemm_astat<0><<<dim3(1, MR / 128), 256, ASTAT_SMEM>>>(G2, WuT, bu, UP, DM, DM / 128);
    // 10) out = LN(X + UP)
    ln_out_kernel<<<MR, 256>>>(x, UP, oln_s, oln_b, out);
}

// round 17
// speedup vs baseline: 1.5914x; 1.5914x over previous
#include <cuda_runtime.h>
#include <cstdint>

// Problem dims
#define TT 2048
#define BB 16
#define DM 1024
#define DB 128
#define DH 512
#define RWS (TT*BB)                 // 32768 rows
#define OUT_MAIN ((size_t)RWS*DM)   // offset of final_mem in d_out

#define NCH 128                     // scan chunks (4 per warp-lane in pass2)
#define CHLEN (TT/NCH)              // 16
#define LANES (BB*DB)               // 2048 scan lanes

#define ASTAT_SMEM ((8 + 2) * 2048 * 4)   // 81920 bytes: A[8 tiles] + B[2 bufs]

// Scratch (device globals; no runtime allocation allowed)
__device__ float g_H   [RWS*DB];
__device__ float g_Wpre[RWS*DB];
__device__ float g_M   [RWS*DB];
__device__ float g_G   [RWS*DB];
__device__ float g_U1  [RWS*DH];
__device__ float g_G2  [RWS*DB];
__device__ float g_UP  [RWS*DM];
__device__ float g_Aseg [NCH*LANES];
__device__ float g_Cseg [NCH*LANES];
__device__ float g_Carry[NCH*LANES];
// transformed weights: [N][K], k-permuted+swizzled, tf32-truncated
__device__ float g_WbT [DB*DM];
__device__ float g_WwT [DB*DB];
__device__ float g_WrT [DB*DB];
__device__ float g_W1T [DH*DB];
__device__ float g_W2T [DB*DH];
__device__ float g_WuT [DM*DB];

// ---------------------------------------------------------------------------
__device__ __forceinline__ float to_tf32(float x) {
    uint32_t u;
    asm("cvt.rna.tf32.f32 %0, %1;" : "=r"(u) : "f"(x));
    return __uint_as_float(u);
}

__device__ __forceinline__ void mma_tf32(float* d, const float* a, const float* b) {
    asm volatile(
        "mma.sync.aligned.m16n8k8.row.col.f32.tf32.tf32.f32 "
        "{%0,%1,%2,%3}, {%4,%5,%6,%7}, {%8,%9}, {%0,%1,%2,%3};"
        : "+f"(d[0]), "+f"(d[1]), "+f"(d[2]), "+f"(d[3])
        : "r"(__float_as_uint(a[0])), "r"(__float_as_uint(a[1])),
          "r"(__float_as_uint(a[2])), "r"(__float_as_uint(a[3])),
          "r"(__float_as_uint(b[0])), "r"(__float_as_uint(b[1])));
}

__device__ __forceinline__ void cp_async16(void* smem_dst, const void* gmem_src) {
    unsigned dst = (unsigned)__cvta_generic_to_shared(smem_dst);
    asm volatile("cp.async.ca.shared.global [%0], [%1], 16;" :: "r"(dst), "l"(gmem_src));
}
__device__ __forceinline__ void cp_async_commit() {
    asm volatile("cp.async.commit_group;");
}
__device__ __forceinline__ void cp_async_wait_all() {
    asm volatile("cp.async.wait_group 0;" ::: "memory");
}

// ---------------------------------------------------------------------------
// Weight prep: Wt[n][pos(k)] = tf32(W[k][n]), pos within 16-k groups:
//   kk=k&15: pos = g*16 + ((kk&3) ^ ((n>>1)&3))*4 + (kk>>2)
// ---------------------------------------------------------------------------
__global__ void prep_weights(const float* __restrict__ Wb, const float* __restrict__ Ww,
                             const float* __restrict__ Wr, const float* __restrict__ W1,
                             const float* __restrict__ W2, const float* __restrict__ Wu,
                             float* __restrict__ WbT, float* __restrict__ WwT,
                             float* __restrict__ WrT, float* __restrict__ W1T,
                             float* __restrict__ W2T, float* __restrict__ WuT)
{
    const int wsel = blockIdx.y;
    const float* W; float* Wt; int K, N;
    switch (wsel) {
        case 0: W = Wb; Wt = WbT; K = DM; N = DB; break;
        case 1: W = Ww; Wt = WwT; K = DB; N = DB; break;
        case 2: W = Wr; Wt = WrT; K = DB; N = DB; break;
        case 3: W = W1; Wt = W1T; K = DB; N = DH; break;
        case 4: W = W2; Wt = W2T; K = DH; N = DB; break;
        default: W = Wu; Wt = WuT; K = DB; N = DM; break;
    }
    const int idx = blockIdx.x * blockDim.x + threadIdx.x;
    if (idx >= K * N) return;
    const int k = idx / N, n = idx % N;
    const int kk = k & 15, g = k >> 4;
    const int pos = g * 16 + (((kk & 3) ^ ((n >> 1) & 3)) << 2) + (kk >> 2);
    Wt[(size_t)n * K + pos] = to_tf32(W[idx]);
}

// ---------------------------------------------------------------------------
// Shared compute for one k-tile (BM=128, BN=128, BK=16 layout)
// ---------------------------------------------------------------------------
#define COMPUTE_TILE(as_, bs_)                                                  \
    {                                                                           \
        float4 a0[2], a1[2];                                                    \
        _Pragma("unroll")                                                       \
        for (int mt = 0; mt < 2; mt++) {                                        \
            const int r0 = wm * 32 + mt * 16 + gid;                             \
            const int r1 = r0 + 8;                                              \
            a0[mt] = *(const float4*)&(as_)[r0 * 16 + ((tig ^ ((r0 >> 1) & 3)) << 2)]; \
            a1[mt] = *(const float4*)&(as_)[r1 * 16 + ((tig ^ ((r1 >> 1) & 3)) << 2)]; \
        }                                                                       \
        _Pragma("unroll")                                                       \
        for (int nh = 0; nh < 2; nh++) {                                        \
            float4 b4[4];                                                       \
            _Pragma("unroll")                                                   \
            for (int q = 0; q < 4; q++) {                                       \
                const int n = wn * 64 + (nh * 4 + q) * 8 + gid;                 \
                b4[q] = *(const float4*)&(bs_)[n * 16 + ((tig ^ ((n >> 1) & 3)) << 2)]; \
            }                                                                   \
            _Pragma("unroll")                                                   \
            for (int ph = 0; ph < 2; ph++) {                                    \
                _Pragma("unroll")                                               \
                for (int mt = 0; mt < 2; mt++) {                                \
                    float af[4];                                                \
                    if (ph == 0) { af[0] = a0[mt].x; af[1] = a1[mt].x;          \
                                   af[2] = a0[mt].y; af[3] = a1[mt].y; }        \
                    else         { af[0] = a0[mt].z; af[1] = a1[mt].z;          \
                                   af[2] = a0[mt].w; af[3] = a1[mt].w; }        \
                    _Pragma("unroll")                                           \
                    for (int q = 0; q < 4; q++) {                               \
                        float bf[2];                                            \
                        bf[0] = (ph == 0) ? b4[q].x : b4[q].z;                  \
                        bf[1] = (ph == 0) ? b4[q].y : b4[q].w;                  \
                        mma_tf32(acc[mt][nh * 4 + q], af, bf);                  \
                    }                                                           \
                }                                                               \
            }                                                                   \
        }                                                                       \
    }

// Pair (k, k+4) of a 16-k group lands at adjacent smem offsets -> float2 store.
#define A_STORE(dst, row, q2, sw, v0, v1)                                       \
    {                                                                           \
        float* as_ = (dst) + (row) * 16;                                        \
        *(float2*)&as_[((0 ^ (sw)) << 2) + (q2)] =                              \
            make_float2(to_tf32((v0).x), to_tf32((v1).x));                      \
        *(float2*)&as_[((1 ^ (sw)) << 2) + (q2)] =                              \
            make_float2(to_tf32((v0).y), to_tf32((v1).y));                      \
        *(float2*)&as_[((2 ^ (sw)) << 2) + (q2)] =                              \
            make_float2(to_tf32((v0).z), to_tf32((v1).z));                      \
        *(float2*)&as_[((3 ^ (sw)) << 2) + (q2)] =                              \
            make_float2(to_tf32((v0).w), to_tf32((v1).w));                      \
    }

// ---------------------------------------------------------------------------
// TF32 GEMM (R11-frozen): C = act(A@W + bias) (+optional fused residual+LN128)
// ---------------------------------------------------------------------------
template<int ACT, int FUSE_LN>
__global__ void __launch_bounds__(256)
gemm_tf32(const float* __restrict__ A, const float* __restrict__ Wt,
          const float* __restrict__ bias,
          const float* __restrict__ resid,
          const float* __restrict__ ln_s, const float* __restrict__ ln_b,
          float* __restrict__ C, int M, int N, int K)
{
    __shared__ __align__(16) float As[2][128 * 16];
    __shared__ __align__(16) float Bs[2][128 * 16];
    __shared__ float2 red[128][2];

    const int tid  = threadIdx.x;
    const int warp = tid >> 5, lane = tid & 31;
    const int gid  = lane >> 2, tig = lane & 3;
    const int wm   = warp >> 1, wn = warp & 1;
    const int bm   = blockIdx.y, bn = blockIdx.x;

    const float* Ablk = A + (size_t)bm * 128 * K;

    const int aRow = tid >> 1;
    const int aQ   = (tid & 1) * 2;
    const int aSw  = (aRow >> 1) & 3;
    const int bN   = tid >> 1;
    const int bC   = (tid & 1) * 2;
    const float* Bsrc = Wt + (size_t)(bn * 128 + bN) * K + bC * 4;

    float acc[2][8][4];
#pragma unroll
    for (int mt = 0; mt < 2; mt++)
#pragma unroll
        for (int nt = 0; nt < 8; nt++)
#pragma unroll
            for (int i = 0; i < 4; i++) acc[mt][nt][i] = 0.f;

    {
        cp_async16(&Bs[0][bN * 16 + bC * 4],     Bsrc);
        cp_async16(&Bs[0][bN * 16 + bC * 4 + 4], Bsrc + 4);
        cp_async_commit();
        float4 va0 = *(const float4*)(Ablk + (size_t)aRow * K + aQ * 4);
        float4 va1 = *(const float4*)(Ablk + (size_t)aRow * K + aQ * 4 + 4);
        A_STORE(As[0], aRow, aQ, aSw, va0, va1);
        cp_async_wait_all();
    }
    __syncthreads();

    const int nt_tiles = K >> 4;
    int buf = 0;
    for (int t = 0; t < nt_tiles; t++) {
        const bool has_next = (t + 1) < nt_tiles;
        float4 na0, na1;
        if (has_next) {
            const int k0n = (t + 1) << 4;
            cp_async16(&Bs[buf ^ 1][bN * 16 + bC * 4],     Bsrc + k0n);
            cp_async16(&Bs[buf ^ 1][bN * 16 + bC * 4 + 4], Bsrc + k0n + 4);
            cp_async_commit();
            na0 = *(const float4*)(Ablk + (size_t)aRow * K + k0n + aQ * 4);
            na1 = *(const float4*)(Ablk + (size_t)aRow * K + k0n + aQ * 4 + 4);
        }

        const float* as_ = As[buf];
        const float* bs_ = Bs[buf];
        COMPUTE_TILE(as_, bs_);

        if (has_next) {
            A_STORE(As[buf ^ 1], aRow, aQ, aSw, na0, na1);
            cp_async_wait_all();
            __syncthreads();
            buf ^= 1;
        }
    }

    // ---------------- Epilogue ----------------
    if (FUSE_LN) {
        float sum[2][2], sq[2][2];
#pragma unroll
        for (int mt = 0; mt < 2; mt++) { sum[mt][0] = sum[mt][1] = 0.f; sq[mt][0] = sq[mt][1] = 0.f; }

#pragma unroll
        for (int mt = 0; mt < 2; mt++) {
            const int gr0 = bm * 128 + wm * 32 + mt * 16 + gid;
#pragma unroll
            for (int nt = 0; nt < 8; nt++) {
                const int c0 = wn * 64 + nt * 8 + 2 * tig;
                const float bi0 = bias[c0], bi1 = bias[c0 + 1];
                const float2 rA = *(const float2*)(resid + (size_t)gr0 * 128 + c0);
                const float2 rB = *(const float2*)(resid + (size_t)(gr0 + 8) * 128 + c0);
                acc[mt][nt][0] += bi0 + rA.x;
                acc[mt][nt][1] += bi1 + rA.y;
                acc[mt][nt][2] += bi0 + rB.x;
                acc[mt][nt][3] += bi1 + rB.y;
#pragma unroll
                for (int h = 0; h < 2; h++) {
                    const float v0 = acc[mt][nt][2 * h], v1 = acc[mt][nt][2 * h + 1];
                    sum[mt][h] += v0 + v1;
                    sq[mt][h]  += v0 * v0 + v1 * v1;
                }
            }
        }
#pragma unroll
        for (int mt = 0; mt < 2; mt++)
#pragma unroll
            for (int h = 0; h < 2; h++) {
#pragma unroll
                for (int off = 1; off <= 2; off <<= 1) {
                    sum[mt][h] += __shfl_xor_sync(0xffffffffu, sum[mt][h], off);
                    sq[mt][h]  += __shfl_xor_sync(0xffffffffu, sq[mt][h], off);
                }
            }
        if (tig == 0) {
#pragma unroll
            for (int mt = 0; mt < 2; mt++) {
                const int lr0 = wm * 32 + mt * 16 + gid;
                red[lr0][wn]     = make_float2(sum[mt][0], sq[mt][0]);
                red[lr0 + 8][wn] = make_float2(sum[mt][1], sq[mt][1]);
            }
        }
        __syncthreads();

#pragma unroll
        for (int mt = 0; mt < 2; mt++) {
            const int lr0 = wm * 32 + mt * 16 + gid;
            const int gr0 = bm * 128 + lr0;
#pragma unroll
            for (int h = 0; h < 2; h++) {
                const int lr = lr0 + 8 * h;
                const float2 t0 = red[lr][0], t1 = red[lr][1];
                const float mean = (t0.x + t1.x) * (1.f / 128.f);
                const float var  = (t0.y + t1.y) * (1.f / 128.f) - mean * mean;
                const float inv  = rsqrtf(var + 1e-5f);
                float* cp = C + (size_t)(gr0 + 8 * h) * 128;
#pragma unroll
                for (int nt = 0; nt < 8; nt++) {
                    const int c0 = wn * 64 + nt * 8 + 2 * tig;
                    const float s0 = ln_s[c0], s1 = ln_s[c0 + 1];
                    const float b0 = ln_b[c0], b1 = ln_b[c0 + 1];
                    float2 ov;
                    ov.x = (acc[mt][nt][2 * h]     - mean) * inv * s0 + b0;
                    ov.y = (acc[mt][nt][2 * h + 1] - mean) * inv * s1 + b1;
                    *(float2*)(cp + c0) = ov;
                }
            }
        }
    } else {
#pragma unroll
        for (int mt = 0; mt < 2; mt++) {
            const int r0 = bm * 128 + wm * 32 + mt * 16 + gid;
#pragma unroll
            for (int nt = 0; nt < 8; nt++) {
                const int c0 = bn * 128 + wn * 64 + nt * 8 + 2 * tig;
                const float bi0 = bias[c0], bi1 = bias[c0 + 1];
                float v0 = acc[mt][nt][0] + bi0;
                float v1 = acc[mt][nt][1] + bi1;
                float v2 = acc[mt][nt][2] + bi0;
                float v3 = acc[mt][nt][3] + bi1;
                if (ACT == 1) { v0 = tanhf(v0); v1 = tanhf(v1); v2 = tanhf(v2); v3 = tanhf(v3); }
                else if (ACT == 2) { v0 = fmaxf(v0, 0.f); v1 = fmaxf(v1, 0.f); v2 = fmaxf(v2, 0.f); v3 = fmaxf(v3, 0.f); }
                *(float2*)(C + (size_t)r0 * N + c0)       = make_float2(v0, v1);
                *(float2*)(C + (size_t)(r0 + 8) * N + c0) = make_float2(v2, v3);
            }
        }
    }
}

// ---------------------------------------------------------------------------
// A-stationary GEMM (R11-frozen): K=128, wide N; stage all 8 A k-tiles once,
// stream B per n-strip with double buffer. ACT: 0 none, 2 relu.
// ---------------------------------------------------------------------------
template<int ACT>
__global__ void __launch_bounds__(256)
gemm_astat(const float* __restrict__ A, const float* __restrict__ Wt,
           const float* __restrict__ bias, float* __restrict__ C,
           int N, int NS)
{
    extern __shared__ __align__(16) float smem[];
    float* As = smem;              // 8 tiles * 2048
    float* Bs = smem + 8 * 2048;   // 2 bufs  * 2048
    const int K = 128;

    const int tid  = threadIdx.x;
    const int warp = tid >> 5, lane = tid & 31;
    const int gid  = lane >> 2, tig = lane & 3;
    const int wm   = warp >> 1, wn = warp & 1;
    const int bm   = blockIdx.y;

    const float* Ablk = A + (size_t)bm * 128 * K;
    const int aRow = tid >> 1;
    const int aQ   = (tid & 1) * 2;
    const int aSw  = (aRow >> 1) & 3;
    const int bN   = tid >> 1;
    const int bC   = (tid & 1) * 2;

    // stage ALL A k-tiles once + first B tile
    {
        const float* b0 = Wt + (size_t)bN * K + bC * 4;
        cp_async16(&Bs[bN * 16 + bC * 4],     b0);
        cp_async16(&Bs[bN * 16 + bC * 4 + 4], b0 + 4);
        cp_async_commit();
#pragma unroll
        for (int t = 0; t < 8; t++) {
            float4 va0 = *(const float4*)(Ablk + (size_t)aRow * K + t * 16 + aQ * 4);
            float4 va1 = *(const float4*)(Ablk + (size_t)aRow * K + t * 16 + aQ * 4 + 4);
            A_STORE(As + t * 2048, aRow, aQ, aSw, va0, va1);
        }
        cp_async_wait_all();
    }
    __syncthreads();

    int buf = 0;
    const int qtot = NS * 8;
    for (int s = 0; s < NS; s++) {
        float acc[2][8][4];
#pragma unroll
        for (int mt = 0; mt < 2; mt++)
#pragma unroll
            for (int nt = 0; nt < 8; nt++)
#pragma unroll
                for (int i = 0; i < 4; i++) acc[mt][nt][i] = 0.f;

#pragma unroll
        for (int t = 0; t < 8; t++) {
            const int q = s * 8 + t;
            const bool hn = (q + 1) < qtot;
            if (hn) {
                const int qs = (q + 1) >> 3, qt = (q + 1) & 7;
                const float* nb = Wt + (size_t)(qs * 128 + bN) * K + qt * 16 + bC * 4;
                cp_async16(&Bs[(buf ^ 1) * 2048 + bN * 16 + bC * 4],     nb);
                cp_async16(&Bs[(buf ^ 1) * 2048 + bN * 16 + bC * 4 + 4], nb + 4);
                cp_async_commit();
            }

            const float* as_ = As + t * 2048;
            const float* bs_ = Bs + buf * 2048;
            COMPUTE_TILE(as_, bs_);

            if (hn) {
                cp_async_wait_all();
                __syncthreads();
                buf ^= 1;
            }
        }

        // strip epilogue (overlaps next strip's B prefetch already in flight)
#pragma unroll
        for (int mt = 0; mt < 2; mt++) {
            const int r0 = bm * 128 + wm * 32 + mt * 16 + gid;
#pragma unroll
            for (int nt = 0; nt < 8; nt++) {
                const int c0 = s * 128 + wn * 64 + nt * 8 + 2 * tig;
                const float bi0 = bias[c0], bi1 = bias[c0 + 1];
                float v0 = acc[mt][nt][0] + bi0;
                float v1 = acc[mt][nt][1] + bi1;
                float v2 = acc[mt][nt][2] + bi0;
                float v3 = acc[mt][nt][3] + bi1;
                if (ACT == 2) { v0 = fmaxf(v0, 0.f); v1 = fmaxf(v1, 0.f); v2 = fmaxf(v2, 0.f); v3 = fmaxf(v3, 0.f); }
                *(float2*)(C + (size_t)r0 * N + c0)       = make_float2(v0, v1);
                *(float2*)(C + (size_t)(r0 + 8) * N + c0) = make_float2(v2, v3);
            }
        }
    }
}

// ---------------------------------------------------------------------------
// Scan (3-pass). NCH=128 chunks of 16 steps; pass2 composes 4 chunks/lane.
// ---------------------------------------------------------------------------
__global__ void scan_pass1(const float* __restrict__ Wpre,
                           const unsigned char* __restrict__ mask,
                           const float* __restrict__ dlogit,
                           float* __restrict__ Aseg, float* __restrict__ Cseg)
{
    const int tid2 = blockIdx.x * blockDim.x + threadIdx.x;  // 0..1023
    const int ch   = blockIdx.y;
    const int b    = tid2 >> 6;
    const int jp   = tid2 & 63;
    const int base = b * 128 + 2 * jp;
    const float2 dl = *(const float2*)(dlogit + 2 * jp);
    const float d0 = 1.f / (1.f + expf(-dl.x)), d1 = 1.f / (1.f + expf(-dl.y));
    float A0 = 1.f, C0 = 0.f, A1 = 1.f, C1 = 0.f;
    const int t0 = ch * CHLEN;
#pragma unroll 4
    for (int t = t0; t < t0 + CHLEN; t++) {
        const bool mk = mask[t * BB + b] != 0;
        const float2 w = *(const float2*)(Wpre + (size_t)t * LANES + base);
        if (!mk) {
            A0 *= d0; C0 = d0 * C0 + (1.f - d0) * w.x;
            A1 *= d1; C1 = d1 * C1 + (1.f - d1) * w.y;
        }
    }
    *(float2*)(Aseg + ch * LANES + base) = make_float2(A0, A1);
    *(float2*)(Cseg + ch * LANES + base) = make_float2(C0, C1);
}

__global__ void scan_pass2(const float* __restrict__ Aseg,
                           const float* __restrict__ Cseg,
                           const float* __restrict__ mem0,
                           float* __restrict__ Carry,
                           float* __restrict__ outFinal)
{
    const int idx  = blockIdx.x * 8 + (threadIdx.x >> 5);    // lane 0..2047
    const int lane = threadIdx.x & 31;                        // group of 4 chunks
    const int c0i  = 4 * lane;
    float A[4], C[4];
#pragma unroll
    for (int i = 0; i < 4; i++) {
        A[i] = Aseg[(c0i + i) * LANES + idx];
        C[i] = Cseg[(c0i + i) * LANES + idx];
    }
    // compose the 4 chunk affines (in time order)
    const float A01 = A[1] * A[0];
    const float C01 = A[1] * C[0] + C[1];
    const float A23 = A[3] * A[2];
    const float C23 = A[3] * C[2] + C[3];
    float Av = A23 * A01;
    float Cv = A23 * C01 + C23;
#pragma unroll
    for (int off = 1; off < 32; off <<= 1) {
        const float pA = __shfl_up_sync(0xffffffffu, Av, off);
        const float pC = __shfl_up_sync(0xffffffffu, Cv, off);
        if (lane >= off) { Cv = Av * pC + Cv; Av = Av * pA; }
    }
    const float m0 = mem0[idx];
    const float incl = Av * m0 + Cv;                 // mem after chunks 0..4l+3
    const float prev = __shfl_up_sync(0xffffffffu, incl, 1);
    float e = (lane == 0) ? m0 : prev;               // mem entering chunk 4l
#pragma unroll
    for (int i = 0; i < 4; i++) {
        Carry[(c0i + i) * LANES + idx] = e;
        e = A[i] * e + C[i];
    }
    if (lane == 31) outFinal[idx] = incl;
}

__global__ void scan_pass3(const float* __restrict__ Wpre,
                           const unsigned char* __restrict__ mask,
                           const float* __restrict__ dlogit,
                           const float* __restrict__ Carry,
                           float* __restrict__ Mbuf)
{
    const int tid2 = blockIdx.x * blockDim.x + threadIdx.x;  // 0..1023
    const int ch   = blockIdx.y;
    const int b    = tid2 >> 6;
    const int jp   = tid2 & 63;
    const int base = b * 128 + 2 * jp;
    const float2 dl = *(const float2*)(dlogit + 2 * jp);
    const float d0 = 1.f / (1.f + expf(-dl.x)), d1 = 1.f / (1.f + expf(-dl.y));
    float2 m = *(const float2*)(Carry + ch * LANES + base);
    const int t0 = ch * CHLEN;
#pragma unroll 4
    for (int t = t0; t < t0 + CHLEN; t++) {
        *(float2*)(Mbuf + (size_t)t * LANES + base) = m;
        const bool mk = mask[t * BB + b] != 0;
        const float2 w = *(const float2*)(Wpre + (size_t)t * LANES + base);
        if (!mk) {
            m.x = d0 * m.x + (1.f - d0) * w.x;
            m.y = d1 * m.y + (1.f - d1) * w.y;
        }
    }
}

// ---------------------------------------------------------------------------
// Final: out = LN(X + UP) over D_MODEL=1024, single-pass stats.
// ---------------------------------------------------------------------------
__global__ void __launch_bounds__(256)
ln_out_kernel(const float* __restrict__ X, const float* __restrict__ UP,
              const float* __restrict__ s, const float* __restrict__ b,
              float* __restrict__ O)
{
    __shared__ float2 red[8];
    const int row = blockIdx.x;
    const int tid = threadIdx.x;
    const int lane = tid & 31, wid = tid >> 5;
    const float4 xv = *(const float4*)(X  + (size_t)row * DM + tid * 4);
    const float4 uv = *(const float4*)(UP + (size_t)row * DM + tid * 4);
    float v[4] = {xv.x + uv.x, xv.y + uv.y, xv.z + uv.z, xv.w + uv.w};
    float2 st = make_float2(0.f, 0.f);
#pragma unroll
    for (int i = 0; i < 4; i++) { st.x += v[i]; st.y += v[i] * v[i]; }
#pragma unroll
    for (int off = 16; off >= 1; off >>= 1) {
        st.x += __shfl_xor_sync(0xffffffffu, st.x, off);
        st.y += __shfl_xor_sync(0xffffffffu, st.y, off);
    }
    if (lane == 0) red[wid] = st;
    __syncthreads();
    float2 t = (lane < 8) ? red[lane] : make_float2(0.f, 0.f);
#pragma unroll
    for (int off = 4; off >= 1; off >>= 1) {
        t.x += __shfl_xor_sync(0xffffffffu, t.x, off);
        t.y += __shfl_xor_sync(0xffffffffu, t.y, off);
    }
    t.x = __shfl_sync(0xffffffffu, t.x, 0);
    t.y = __shfl_sync(0xffffffffu, t.y, 0);
    const float mean = t.x * (1.f / DM);
    const float var  = t.y * (1.f / DM) - mean * mean;
    const float inv  = rsqrtf(var + 1e-5f);
    const float4 sv = *(const float4*)(s + tid * 4);
    const float4 bv = *(const float4*)(b + tid * 4);
    float4 ov;
    ov.x = (v[0] - mean) * inv * sv.x + bv.x;
    ov.y = (v[1] - mean) * inv * sv.y + bv.y;
    ov.z = (v[2] - mean) * inv * sv.z + bv.z;
    ov.w = (v[3] - mean) * inv * sv.w + bv.w;
    *(float4*)(O + (size_t)row * DM + tid * 4) = ov;
}

// ---------------------------------------------------------------------------
extern "C" void kernel_launch(void* const* d_in, const int* in_sizes, int n_in,
                              void* d_out, int out_size)
{
    const float*         x      = (const float*)d_in[0];
    const unsigned char* mask   = (const unsigned char*)d_in[1];
    const float*         mem0   = (const float*)d_in[2];
    const float*         Wb     = (const float*)d_in[3];
    const float*         b_bot  = (const float*)d_in[4];
    const float*         Wu     = (const float*)d_in[5];
    const float*         bu     = (const float*)d_in[6];
    const float*         Wr     = (const float*)d_in[7];
    const float*         br     = (const float*)d_in[8];
    const float*         Ww     = (const float*)d_in[9];
    const float*         bw     = (const float*)d_in[10];
    const float*         dlog   = (const float*)d_in[11];
    const float*         ff_w1  = (const float*)d_in[12];
    const float*         ff_b1  = (const float*)d_in[13];
    const float*         ff_w2  = (const float*)d_in[14];
    const float*         ff_b2  = (const float*)d_in[15];
    const float*         mln_s  = (const float*)d_in[16];
    const float*         mln_b  = (const float*)d_in[17];
    const float*         fln_s  = (const float*)d_in[18];
    const float*         fln_b  = (const float*)d_in[19];
    const float*         oln_s  = (const float*)d_in[20];
    const float*         oln_b  = (const float*)d_in[21];

    float* out = (float*)d_out;

    float *H, *Wpre, *M, *G, *U1, *G2, *UP, *Aseg, *Cseg, *Carry;
    float *WbT, *WwT, *WrT, *W1T, *W2T, *WuT;
    cudaGetSymbolAddress((void**)&H,     g_H);
    cudaGetSymbolAddress((void**)&Wpre,  g_Wpre);
    cudaGetSymbolAddress((void**)&M,     g_M);
    cudaGetSymbolAddress((void**)&G,     g_G);
    cudaGetSymbolAddress((void**)&U1,    g_U1);
    cudaGetSymbolAddress((void**)&G2,    g_G2);
    cudaGetSymbolAddress((void**)&UP,    g_UP);
    cudaGetSymbolAddress((void**)&Aseg,  g_Aseg);
    cudaGetSymbolAddress((void**)&Cseg,  g_Cseg);
    cudaGetSymbolAddress((void**)&Carry, g_Carry);
    cudaGetSymbolAddress((void**)&WbT,   g_WbT);
    cudaGetSymbolAddress((void**)&WwT,   g_WwT);
    cudaGetSymbolAddress((void**)&WrT,   g_WrT);
    cudaGetSymbolAddress((void**)&W1T,   g_W1T);
    cudaGetSymbolAddress((void**)&W2T,   g_W2T);
    cudaGetSymbolAddress((void**)&WuT,   g_WuT);

    static int attr_set = 0;
    if (!attr_set) {
        cudaFuncSetAttribute(gemm_astat<0>, cudaFuncAttributeMaxDynamicSharedMemorySize, ASTAT_SMEM);
        cudaFuncSetAttribute(gemm_astat<2>, cudaFuncAttributeMaxDynamicSharedMemorySize, ASTAT_SMEM);
        attr_set = 1;
    }

    const int MR = RWS;  // 32768 rows

    // 0) transform weights (transpose + k-perm + swizzle + tf32)
    prep_weights<<<dim3(512, 6), 256>>>(Wb, Ww, Wr, ff_w1, ff_w2, Wu,
                                        WbT, WwT, WrT, W1T, W2T, WuT);
    // 1) H = X @ Wb + bb
    gemm_tf32<0,0><<<dim3(1, MR / 128), 256>>>(x, WbT, b_bot, nullptr, nullptr, nullptr,
                                               H, MR, DB, DM);
    // 2) Wpre = tanh(H @ Ww + bw)
    gemm_tf32<1,0><<<dim3(1, MR / 128), 256>>>(H, WwT, bw, nullptr, nullptr, nullptr,
                                               Wpre, MR, DB, DB);
    // 3) parallel diagonal scan -> M[t], final mem
    scan_pass1<<<dim3(4, NCH), 256>>>(Wpre, mask, dlog, Aseg, Cseg);
    scan_pass2<<<LANES / 8, 256>>>(Aseg, Cseg, mem0, Carry, out + OUT_MAIN);
    scan_pass3<<<dim3(4, NCH), 256>>>(Wpre, mask, dlog, Carry, M);
    // 4+5) G = LN(H + M@Wr + br)  [fused LN]
    gemm_tf32<0,1><<<dim3(1, MR / 128), 256>>>(M, WrT, br, H, mln_s, mln_b,
                                               G, MR, DB, DB);
    // 6) U1 = relu(G @ ff_w1 + ff_b1)  [A-stationary, 4 strips]
    gemm_astat<2><<<dim3(1, MR / 128), 256, ASTAT_SMEM>>>(G, W1T, ff_b1, U1, DH, DH / 128);
    // 7+8) G2 = LN(G + U1@ff_w2 + ff_b2)  [fused LN]
    gemm_tf32<0,1><<<dim3(1, MR / 128), 256>>>(U1, W2T, ff_b2, G, fln_s, fln_b,
                                               G2, MR, DB, DH);
    // 9) UP = G2 @ Wu + bu  [A-stationary, 8 strips]
    gemm_astat<0><<<dim3(1, MR / 128), 256, ASTAT_SMEM>>>(G2, WuT, bu, UP, DM, DM / 128);
    // 10) out = LN(X + UP)
    ln_out_kernel<<<MR, 256>>>(x, UP, oln_s, oln_b, out);
}